// round 17
// baseline (speedup 1.0000x reference)
#include <cuda_runtime.h>
#include <cuda_fp16.h>

// M is 2000 x 20000 fp32 (fixed by setup_inputs).
#define Nn 2000
#define Mm 20000
#define ALPHA 20.0f
#define THR 0.005f
#define EPSc 1e-16f
#define NT 1024
#define NBLK 148                 // one block per SM; all co-resident
#define NS4 5000                 // float4 column slots per row (20000 cols)
#define Q4LIM 904                // slot q=4 valid for tid < 904 (4096+904=5000)
#define SMEM_DYN (5 * 1024 * 16) // v staged as float4[5][1024] = 80 KB

// Static device scratch (no runtime allocation).
__device__ float4 g_C4[(size_t)NBLK * NS4];  // per-block column partials, 11.8 MB
__device__ float4 g_v4[NS4];
__device__ float g_errP[NBLK];
__device__ float g_lossP[NBLK];
__device__ unsigned g_barcnt = 0;

__device__ __forceinline__ unsigned ldcg_u(const unsigned* p) {
    unsigned v;
    asm volatile("ld.global.cg.u32 %0, [%1];" : "=r"(v) : "l"(p));
    return v;
}

// Grid barrier: 148 arrivals (one atomic per block), plain-L2-load polling.
__device__ __forceinline__ void gridbar(unsigned* eps) {
    __syncthreads();
    if (threadIdx.x == 0) {
        unsigned target = *eps + NBLK;
        __threadfence();                        // release
        atomicAdd(&g_barcnt, 1u);
        while (ldcg_u(&g_barcnt) < target) __nanosleep(64);
        __threadfence();                        // acquire
        *eps = target;
    }
    __syncthreads();
}

// Column merge: T_j = sum over 148 block partials; optionally x am (first
// pass, uniform u0) and err vs old v (chk). Writes new v. Static ownership;
// width-8 shuffles executed by ALL lanes (uniform bound, predicated data).
__device__ __forceinline__ float merge_cols(int ss, int ws, int tid,
                                            bool first, bool chk,
                                            float am, float bm) {
    const int p = tid & 7;
    const int sl = tid >> 3;                    // 0..127 uniform; ws <= 34
    const bool valid = (sl < ws);
    const int s = ss + (valid ? sl : 0);
    float4 T = make_float4(0.f, 0.f, 0.f, 0.f);
    if (valid) {
        for (int b = p; b < NBLK; b += 8) {     // fixed order per lane
            float4 c = __ldcg(&g_C4[(size_t)b * NS4 + s]);
            T.x += c.x; T.y += c.y; T.z += c.z; T.w += c.w;
        }
    }
    #pragma unroll
    for (int o = 4; o > 0; o >>= 1) {
        T.x += __shfl_down_sync(0xffffffffu, T.x, o, 8);
        T.y += __shfl_down_sync(0xffffffffu, T.y, o, 8);
        T.z += __shfl_down_sync(0xffffffffu, T.z, o, 8);
        T.w += __shfl_down_sync(0xffffffffu, T.w, o, 8);
    }
    float errA = 0.f;
    if (p == 0 && valid) {
        if (first) { T.x *= am; T.y *= am; T.z *= am; T.w *= am; }
        if (chk) {
            float4 vo = __ldcg(&g_v4[s]);
            errA = fabsf(vo.x * T.x - bm) + fabsf(vo.y * T.y - bm)
                 + fabsf(vo.z * T.z - bm) + fabsf(vo.w * T.w - bm);
        }
        g_v4[s] = make_float4(bm / (T.x + EPSc), bm / (T.y + EPSc),
                              bm / (T.z + EPSc), bm / (T.w + EPSc));
    }
    return errA;
}

// Load one row: compute per-thread S and loss partials (fp32), retain e
// packed fp16 (10 regs instead of 20).
__device__ __forceinline__ void load_row(const float* __restrict__ M,
                                         const float4* sv4, int tid, int r,
                                         uint2* eh, float& S, float& Lp) {
    const float4* Mp = (const float4*)(M + (size_t)r * Mm);
    S = 0.f; Lp = 0.f;
    #pragma unroll
    for (int q = 0; q < 5; ++q) {
        if (q < 4 || tid < Q4LIM) {
            float4 m4 = __ldcg(Mp + tid + 1024 * q);
            float4 vq = sv4[q * 1024 + tid];
            float4 eq;
            eq.x = __expf(-ALPHA * m4.x);
            eq.y = __expf(-ALPHA * m4.y);
            eq.z = __expf(-ALPHA * m4.z);
            eq.w = __expf(-ALPHA * m4.w);
            float p0 = eq.x * vq.x, p1 = eq.y * vq.y;
            float p2 = eq.z * vq.z, p3 = eq.w * vq.w;
            S += (p0 + p1) + (p2 + p3);
            Lp += (p0 * m4.x + p1 * m4.y) + (p2 * m4.z + p3 * m4.w);
            uint2 h;
            *(__half2*)&h.x = __floats2half2_rn(eq.x, eq.y);
            *(__half2*)&h.y = __floats2half2_rn(eq.z, eq.w);
            eh[q] = h;
        } else {
            eh[q] = make_uint2(0u, 0u);
        }
    }
}

__device__ __forceinline__ void acc_C(float4* C, const uint2* eh, float u) {
    #pragma unroll
    for (int q = 0; q < 5; ++q) {
        float2 e01 = __half22float2(*(const __half2*)&eh[q].x);
        float2 e23 = __half22float2(*(const __half2*)&eh[q].y);
        C[q].x = fmaf(u, e01.x, C[q].x);
        C[q].y = fmaf(u, e01.y, C[q].y);
        C[q].z = fmaf(u, e23.x, C[q].z);
        C[q].w = fmaf(u, e23.y, C[q].w);
    }
}

__global__ void __launch_bounds__(NT, 1)
sinkhorn_all(const float* __restrict__ M, float* __restrict__ out) {
    extern __shared__ float4 sv4[];             // v staging: [5][1024]
    __shared__ float s_w[4][32];                // pair-parity double buffer
    __shared__ float sA[NT];
    __shared__ unsigned s_ep;

    const int tid = threadIdx.x, bid = blockIdx.x;
    const int tx = tid & 31;
    const int ty = tid >> 5;
    // static rows: 76 blocks x 14 + 72 x 13 = 2000
    const int rs = bid * 13 + min(bid, 76);
    const int re = rs + 13 + (bid < 76 ? 1 : 0);
    // static merge strip: 116 blocks x 34 + 32 x 33 = 5000 slots
    const int ss = bid * 33 + min(bid, 116);
    const int ws = 33 + (bid < 116 ? 1 : 0);

    if (tid == 0) s_ep = 0;
    __syncthreads();
    const float bm = 1.0f / (float)Mm;
    const float am = 1.0f / (float)Nn;

    // ---- P1: per-block colsum(e) partials. Pure streaming: no shared,
    //      no syncs, no atomics. Rows FORWARD. ----
    {
        float4 CS[5];
        #pragma unroll
        for (int q = 0; q < 5; ++q) CS[q] = make_float4(0.f, 0.f, 0.f, 0.f);
        for (int r = rs; r < re; ++r) {
            const float4* Mp = (const float4*)(M + (size_t)r * Mm);
            #pragma unroll
            for (int q = 0; q < 5; ++q) {
                if (q < 4 || tid < Q4LIM) {
                    float4 m4 = __ldcg(Mp + tid + 1024 * q);
                    CS[q].x += __expf(-ALPHA * m4.x);
                    CS[q].y += __expf(-ALPHA * m4.y);
                    CS[q].z += __expf(-ALPHA * m4.z);
                    CS[q].w += __expf(-ALPHA * m4.w);
                }
            }
        }
        #pragma unroll
        for (int q = 0; q < 5; ++q)
            if (q < 4 || tid < Q4LIM)
                g_C4[(size_t)bid * NS4 + tid + 1024 * q] = CS[q];
    }
    gridbar(&s_ep);

    // ---- v1 = bm / (colsum * am + eps) ----
    merge_cols(ss, ws, tid, true, false, am, bm);
    gridbar(&s_ep);

    // Reference: err only *updated* at cpt==1 / cpt==51 -> exit only at cpt
    // in {1,51,100}. Fused pass k: u_k = am/(K v_k + eps) row-PAIR-wise (one
    // block sync per 2 rows), C = per-block K^T u_k partials (e retained as
    // fp16), loss integrand u*e*v*m accumulated per-thread (fp32, no log).
    bool done = false;
    for (int k = 1; k <= 100 && !done; ++k) {
        const bool chk = (k == 1) || (k == 51);

        // Stage v_k into shared (80 KB), coalesced.
        #pragma unroll
        for (int q = 0; q < 5; ++q)
            if (q < 4 || tid < Q4LIM)
                sv4[q * 1024 + tid] = __ldcg(&g_v4[tid + 1024 * q]);
        __syncthreads();

        float4 C[5];
        #pragma unroll
        for (int q = 0; q < 5; ++q) C[q] = make_float4(0.f, 0.f, 0.f, 0.f);
        float loss_acc = 0.f;
        int pcnt = 0;

        // Row pairs, REVERSE order (L2 reuse from P1's forward sweep).
        int r = re - 1;
        for (; r - 1 >= rs; r -= 2, ++pcnt) {
            uint2 eA[5], eB[5];
            float Sa, La, Sb, Lb;
            load_row(M, sv4, tid, r,     eA, Sa, La);
            load_row(M, sv4, tid, r - 1, eB, Sb, Lb);
            #pragma unroll
            for (int o = 16; o > 0; o >>= 1) {
                Sa += __shfl_xor_sync(0xffffffffu, Sa, o);
                Sb += __shfl_xor_sync(0xffffffffu, Sb, o);
            }
            const int pb = (pcnt & 1) * 2;
            if (tx == 0) { s_w[pb][ty] = Sa; s_w[pb + 1][ty] = Sb; }
            __syncthreads();                    // ONE sync per 2 rows
            float Sva = s_w[pb][tx], Svb = s_w[pb + 1][tx];
            #pragma unroll
            for (int o = 16; o > 0; o >>= 1) {
                Sva += __shfl_xor_sync(0xffffffffu, Sva, o);
                Svb += __shfl_xor_sync(0xffffffffu, Svb, o);
            }
            const float ua = am / (Sva + EPSc);
            const float ub = am / (Svb + EPSc);
            loss_acc = fmaf(ua, La, fmaf(ub, Lb, loss_acc));
            acc_C(C, eA, ua);
            acc_C(C, eB, ub);
        }
        if (r >= rs) {                          // odd leftover row
            uint2 eA[5];
            float Sa, La;
            load_row(M, sv4, tid, r, eA, Sa, La);
            #pragma unroll
            for (int o = 16; o > 0; o >>= 1)
                Sa += __shfl_xor_sync(0xffffffffu, Sa, o);
            const int pb = (pcnt & 1) * 2;
            if (tx == 0) s_w[pb][ty] = Sa;
            __syncthreads();
            float Sva = s_w[pb][tx];
            #pragma unroll
            for (int o = 16; o > 0; o >>= 1)
                Sva += __shfl_xor_sync(0xffffffffu, Sva, o);
            const float ua = am / (Sva + EPSc);
            loss_acc = fmaf(ua, La, loss_acc);
            acc_C(C, eA, ua);
        }

        #pragma unroll
        for (int q = 0; q < 5; ++q)
            if (q < 4 || tid < Q4LIM)
                g_C4[(size_t)bid * NS4 + tid + 1024 * q] = C[q];
        // Per-block loss partial (fixed-order tree).
        sA[tid] = loss_acc;
        __syncthreads();
        for (int o = NT / 2; o > 0; o >>= 1) {
            if (tid < o) sA[tid] += sA[tid + o];
            __syncthreads();
        }
        if (tid == 0) g_lossP[bid] = sA[0];
        gridbar(&s_ep);

        if (k == 100) {                         // exit without convergence
            if (bid == 0) {
                sA[tid] = (tid < NBLK) ? __ldcg(&g_lossP[tid]) : 0.f;
                __syncthreads();
                for (int o = NT / 2; o > 0; o >>= 1) {
                    if (tid < o) sA[tid] += sA[tid + o];
                    __syncthreads();
                }
                if (tid == 0) out[0] = sA[0] * 100.0f;
            }
            done = true;
            continue;
        }

        // ---- Merge: T_j, err at chk (old v), write v_{k+1} ----
        float errA = merge_cols(ss, ws, tid, false, chk, am, bm);
        if (chk) {
            sA[tid] = errA;
            __syncthreads();
            for (int o = NT / 2; o > 0; o >>= 1) {
                if (tid < o) sA[tid] += sA[tid + o];
                __syncthreads();
            }
            if (tid == 0) g_errP[bid] = sA[0];
        }
        gridbar(&s_ep);

        if (chk) {                              // redundant uniform decide
            sA[tid] = (tid < NBLK) ? __ldcg(&g_errP[tid]) : 0.f;
            __syncthreads();
            for (int o = NT / 2; o > 0; o >>= 1) {
                if (tid < o) sA[tid] += sA[tid + o];
                __syncthreads();
            }
            const bool stop = (sA[0] <= THR);
            __syncthreads();
            if (stop) {
                if (bid == 0) {                 // loss uses (u_k, v_k) ✓
                    sA[tid] = (tid < NBLK) ? __ldcg(&g_lossP[tid]) : 0.f;
                    __syncthreads();
                    for (int o = NT / 2; o > 0; o >>= 1) {
                        if (tid < o) sA[tid] += sA[tid + o];
                        __syncthreads();
                    }
                    if (tid == 0) out[0] = sA[0] * 100.0f;
                }
                done = true;
            }
        }
    }

    // Final arrive: last block resets the barrier for the next graph replay.
    __syncthreads();
    if (tid == 0) {
        __threadfence();
        unsigned old = atomicAdd(&g_barcnt, 1u);
        if (old == s_ep + NBLK - 1) atomicExch(&g_barcnt, 0u);
    }
}

extern "C" void kernel_launch(void* const* d_in, const int* in_sizes, int n_in,
                              void* d_out, int out_size) {
    const float* M = (const float*)d_in[0];
    float* out = (float*)d_out;
    // Host-side attribute set (idempotent, not a stream op — capture-safe).
    cudaFuncSetAttribute(sinkhorn_all,
                         cudaFuncAttributeMaxDynamicSharedMemorySize, SMEM_DYN);
    sinkhorn_all<<<NBLK, NT, SMEM_DYN>>>(M, out);
}